// round 2
// baseline (speedup 1.0000x reference)
#include <cuda_runtime.h>

#define BB 64
#define LL 32
#define NTS 64
#define SS 128
#define SDD 512
#define EMBD 512
#define VV 50000
#define EPSF 1e-9f

// ---------------- scratch (device globals, no allocation) ----------------
__device__ float g_chart_p[(size_t)BB * LL * LL * SS];   // [b][i][len][s]   33.5 MB
__device__ float g_chart_f[(size_t)BB * LL * LL * SDD];  // [b][i][len][h]  134 MB
__device__ float g_Gt[SS * SS * NTS];                    // [s][t][a]         4 MB
__device__ float g_sbuf[(size_t)16384 * NTS];            // per-stage scores  4 MB
__device__ float g_w[16384];                             // per-stage weights
__device__ float g_tmpf[(size_t)16384 * SDD];            // per-stage feats  33.5 MB

// ---------------- K_t: transpose G[a][s][t] -> Gt[s][t][a] ----------------
__global__ void k_transG(const float* __restrict__ G) {
    int idx = blockIdx.x * 256 + threadIdx.x;   // over NTS*SS*SS = 1,048,576
    if (idx >= NTS * SS * SS) return;
    int a = idx / (SS * SS);
    int rem = idx % (SS * SS);
    int s = rem / SS;
    int t = rem % SS;
    g_Gt[(s * SS + t) * NTS + a] = G[idx];
}

// ---------------- K0: diagonal preterminal probabilities ----------------
__global__ void k_diag(const int* __restrict__ word, const float* __restrict__ preterm) {
    int cell = blockIdx.x;          // b*LL + i
    int t = threadIdx.x;            // 0..63
    int w = word[cell];
    float v = preterm[(size_t)t * VV + w];
    __shared__ float red[64];
    red[t] = v;
    __syncthreads();
    for (int off = 32; off > 0; off >>= 1) {
        if (t < off) red[t] += red[t + off];
        __syncthreads();
    }
    float inv = 1.0f / (red[0] + EPSF);
    float* dst = g_chart_p + ((size_t)cell * LL + 0) * SS;
    dst[NTS + t] = v * inv;
    dst[t] = 0.0f;
}

// ---------------- K1: feat0 = relu(emb[word] @ Wp + bp) ----------------
__global__ void k_feat0(const int* __restrict__ word, const float* __restrict__ emb,
                        const float* __restrict__ Wp, const float* __restrict__ bp) {
    __shared__ float As[16][64];
    __shared__ float Bs[16][64];
    int tid = threadIdx.x;
    int m0 = blockIdx.x * 64, n0 = blockIdx.y * 64;
    int lm = tid >> 2, lk = (tid & 3) * 4;
    int kb = tid >> 4, nb = (tid & 15) * 4;
    int tx = tid & 15, ty = tid >> 4;

    const float* arow = emb + (size_t)word[m0 + lm] * EMBD;
    float acc[4][4] = {};

    for (int k0 = 0; k0 < EMBD; k0 += 16) {
        float4 a4 = *(const float4*)(arow + k0 + lk);
        As[lk + 0][lm] = a4.x; As[lk + 1][lm] = a4.y;
        As[lk + 2][lm] = a4.z; As[lk + 3][lm] = a4.w;
        float4 b4 = *(const float4*)(Wp + (size_t)(k0 + kb) * SDD + n0 + nb);
        *(float4*)&Bs[kb][nb] = b4;
        __syncthreads();
#pragma unroll
        for (int k = 0; k < 16; k++) {
            float4 av = *(float4*)&As[k][ty * 4];
            float4 bv = *(float4*)&Bs[k][tx * 4];
            acc[0][0] += av.x * bv.x; acc[0][1] += av.x * bv.y; acc[0][2] += av.x * bv.z; acc[0][3] += av.x * bv.w;
            acc[1][0] += av.y * bv.x; acc[1][1] += av.y * bv.y; acc[1][2] += av.y * bv.z; acc[1][3] += av.y * bv.w;
            acc[2][0] += av.z * bv.x; acc[2][1] += av.z * bv.y; acc[2][2] += av.z * bv.z; acc[2][3] += av.z * bv.w;
            acc[3][0] += av.w * bv.x; acc[3][1] += av.w * bv.y; acc[3][2] += av.w * bv.z; acc[3][3] += av.w * bv.w;
        }
        __syncthreads();
    }
#pragma unroll
    for (int i = 0; i < 4; i++) {
        int r = m0 + ty * 4 + i;
        float* dst = g_chart_f + ((size_t)r * LL + 0) * SDD;
#pragma unroll
        for (int j = 0; j < 4; j++) {
            int c = n0 + tx * 4 + j;
            float v = acc[i][j] + bp[c];
            dst[c] = v > 0.0f ? v : 0.0f;
        }
    }
}

// ---------------- K2: score GEMM  S[r][a] = sum_{s,t} lp[s] rp[t] Gt[s][t][a] ----------------
// BM=32 rows, BN=64 (all a), 128 threads, TM=2, TN=8. Dynamic smem 64 KB.
__global__ void k_scores(int ln, int n, int R) {
    extern __shared__ float smem[];
    float* lpT = smem;           // [128 s][32 c]
    float* rpT = smem + 4096;    // [128 t][32 c]
    float* gs  = smem + 8192;    // [128 t][64 a]

    int tid = threadIdx.x;
    int r0 = blockIdx.x * 32;

    // load lp/rp rows (once per block), transposed into smem
    {
        int c = tid >> 2, q = tid & 3;
        int r = r0 + c;
        bool valid = r < R;
        const float* lp = g_chart_p;
        const float* rp = g_chart_p;
        if (valid) {
            int d1 = r / (BB * n);
            int rem = r % (BB * n);
            int b = rem / n, j = rem % n;
            lp = g_chart_p + (((size_t)b * LL + j) * LL + d1) * SS;
            rp = g_chart_p + (((size_t)b * LL + (j + d1 + 1)) * LL + (ln - d1 - 2)) * SS;
        }
        float4 z4 = make_float4(0, 0, 0, 0);
#pragma unroll
        for (int i = 0; i < 32; i += 4) {
            int t = q * 32 + i;
            float4 l4 = valid ? *(const float4*)(lp + t) : z4;
            float4 r4 = valid ? *(const float4*)(rp + t) : z4;
            lpT[(t + 0) * 32 + c] = l4.x; lpT[(t + 1) * 32 + c] = l4.y;
            lpT[(t + 2) * 32 + c] = l4.z; lpT[(t + 3) * 32 + c] = l4.w;
            rpT[(t + 0) * 32 + c] = r4.x; rpT[(t + 1) * 32 + c] = r4.y;
            rpT[(t + 2) * 32 + c] = r4.z; rpT[(t + 3) * 32 + c] = r4.w;
        }
    }
    __syncthreads();

    int ty = tid >> 3;   // 0..15 -> c0 = ty*2
    int tx = tid & 7;    // 0..7  -> a0 = tx*8
    float acc0[8] = {};
    float acc1[8] = {};

    for (int s = 0; s < SS; s++) {
        const float* gsl = g_Gt + (size_t)s * (SS * NTS);
#pragma unroll
        for (int i = 0; i < 16; i++) {
            int idx = (i * 128 + tid) * 4;
            *(float4*)&gs[idx] = *(const float4*)(gsl + idx);
        }
        __syncthreads();
        float2 lv = *(float2*)&lpT[s * 32 + ty * 2];
#pragma unroll 8
        for (int t = 0; t < SS; t++) {
            float2 rv = *(float2*)&rpT[t * 32 + ty * 2];
            float p0 = lv.x * rv.x;
            float p1 = lv.y * rv.y;
            float4 g0 = *(float4*)&gs[t * 64 + tx * 8];
            float4 g1 = *(float4*)&gs[t * 64 + tx * 8 + 4];
            acc0[0] += p0 * g0.x; acc0[1] += p0 * g0.y; acc0[2] += p0 * g0.z; acc0[3] += p0 * g0.w;
            acc0[4] += p0 * g1.x; acc0[5] += p0 * g1.y; acc0[6] += p0 * g1.z; acc0[7] += p0 * g1.w;
            acc1[0] += p1 * g0.x; acc1[1] += p1 * g0.y; acc1[2] += p1 * g0.z; acc1[3] += p1 * g0.w;
            acc1[4] += p1 * g1.x; acc1[5] += p1 * g1.y; acc1[6] += p1 * g1.z; acc1[7] += p1 * g1.w;
        }
        __syncthreads();
    }

    // epilogue
    int a0 = tx * 8;
    int r_a = r0 + ty * 2;
    if (r_a < R) {
        *(float4*)&g_sbuf[(size_t)r_a * NTS + a0]     = make_float4(acc0[0], acc0[1], acc0[2], acc0[3]);
        *(float4*)&g_sbuf[(size_t)r_a * NTS + a0 + 4] = make_float4(acc0[4], acc0[5], acc0[6], acc0[7]);
    }
    int r_b = r_a + 1;
    if (r_b < R) {
        *(float4*)&g_sbuf[(size_t)r_b * NTS + a0]     = make_float4(acc1[0], acc1[1], acc1[2], acc1[3]);
        *(float4*)&g_sbuf[(size_t)r_b * NTS + a0 + 4] = make_float4(acc1[4], acc1[5], acc1[6], acc1[7]);
    }
}

// ---------------- K3: combine over d -> p (chart_p) and weights w ----------------
__global__ void k_combine(int ln, int n) {
    int cell = blockIdx.x;          // b*n + j
    int b = cell / n, j = cell % n;
    int t = threadIdx.x;            // 64 threads
    int nd = ln - 1;
    __shared__ float sm_mass[32];
    __shared__ float sm_M;

    if (t < nd) {
        int r = (t * BB + b) * n + j;
        const float* sp = g_sbuf + (size_t)r * NTS;
        float m = 0.0f;
        for (int a = 0; a < NTS; a++) m += sp[a];
        sm_mass[t] = m;
    }
    __syncthreads();
    if (t == 0) {
        float M = 0.0f;
        for (int d = 0; d < nd; d++) M += sm_mass[d];
        sm_M = M;
    }
    __syncthreads();
    float Minv = 1.0f / (sm_M + EPSF);
    if (t < nd) {
        int r = (t * BB + b) * n + j;
        g_w[r] = sm_mass[t] * Minv;
    }
    float sc = 0.0f;
    for (int d = 0; d < nd; d++) {
        int r = (d * BB + b) * n + j;
        sc += g_sbuf[(size_t)r * NTS + t];
    }
    float* dst = g_chart_p + (((size_t)b * LL + j) * LL + (ln - 1)) * SS;
    dst[t] = sc * Minv;
    dst[NTS + t] = 0.0f;
}

// ---------------- K4: feature GEMM  tmpf[r] = w[r]*relu([lf|rf]@Wm + bm) ----------------
__global__ void k_feat(int ln, int n, int R,
                       const float* __restrict__ Wm, const float* __restrict__ bm) {
    __shared__ float As[16][64];
    __shared__ float Bs[16][64];
    int tid = threadIdx.x;
    int m0 = blockIdx.x * 64, n0 = blockIdx.y * 64;
    int lm = tid >> 2, lkq = (tid & 3) * 4;
    int kb = tid >> 4, nb = (tid & 15) * 4;
    int tx = tid & 15, ty = tid >> 4;

    int r = m0 + lm;
    bool valid = r < R;
    const float* lf = g_chart_f;
    const float* rf = g_chart_f;
    if (valid) {
        int d1 = r / (BB * n);
        int rem = r % (BB * n);
        int b = rem / n, j = rem % n;
        lf = g_chart_f + (((size_t)b * LL + j) * LL + d1) * SDD;
        rf = g_chart_f + (((size_t)b * LL + (j + d1 + 1)) * LL + (ln - d1 - 2)) * SDD;
    }
    float4 z4 = make_float4(0, 0, 0, 0);
    float acc[4][4] = {};

    for (int k0 = 0; k0 < 2 * SDD; k0 += 16) {
        const float* src = (k0 < SDD) ? lf : rf;
        int kk = k0 + lkq - (k0 < SDD ? 0 : SDD);
        float4 a4 = valid ? *(const float4*)(src + kk) : z4;
        As[lkq + 0][lm] = a4.x; As[lkq + 1][lm] = a4.y;
        As[lkq + 2][lm] = a4.z; As[lkq + 3][lm] = a4.w;
        float4 b4 = *(const float4*)(Wm + (size_t)(k0 + kb) * SDD + n0 + nb);
        *(float4*)&Bs[kb][nb] = b4;
        __syncthreads();
#pragma unroll
        for (int k = 0; k < 16; k++) {
            float4 av = *(float4*)&As[k][ty * 4];
            float4 bv = *(float4*)&Bs[k][tx * 4];
            acc[0][0] += av.x * bv.x; acc[0][1] += av.x * bv.y; acc[0][2] += av.x * bv.z; acc[0][3] += av.x * bv.w;
            acc[1][0] += av.y * bv.x; acc[1][1] += av.y * bv.y; acc[1][2] += av.y * bv.z; acc[1][3] += av.y * bv.w;
            acc[2][0] += av.z * bv.x; acc[2][1] += av.z * bv.y; acc[2][2] += av.z * bv.z; acc[2][3] += av.z * bv.w;
            acc[3][0] += av.w * bv.x; acc[3][1] += av.w * bv.y; acc[3][2] += av.w * bv.z; acc[3][3] += av.w * bv.w;
        }
        __syncthreads();
    }
#pragma unroll
    for (int i = 0; i < 4; i++) {
        int rr = m0 + ty * 4 + i;
        if (rr < R) {
            float wgt = g_w[rr];
#pragma unroll
            for (int j = 0; j < 4; j++) {
                int c = n0 + tx * 4 + j;
                float v = acc[i][j] + bm[c];
                v = v > 0.0f ? v : 0.0f;
                g_tmpf[(size_t)rr * SDD + c] = v * wgt;
            }
        }
    }
}

// ---------------- K5: reduce weighted feats over d -> chart_f ----------------
__global__ void k_reduce_f(int ln, int n) {
    int idx = blockIdx.x * 256 + threadIdx.x;    // over BB*n*SDD
    int tot = BB * n * SDD;
    if (idx >= tot) return;
    int h = idx & (SDD - 1);
    int cell = idx >> 9;
    int b = cell / n, j = cell % n;
    float acc = 0.0f;
    for (int d1 = 0; d1 < ln - 1; d1++) {
        int r = (d1 * BB + b) * n + j;
        acc += g_tmpf[(size_t)r * SDD + h];
    }
    g_chart_f[(((size_t)b * LL + j) * LL + (ln - 1)) * SDD + h] = acc;
}

// ---------------- K6: root ----------------
__global__ void k_root(const float* __restrict__ starts, float* __restrict__ out) {
    int b = blockIdx.x;
    int t = threadIdx.x;   // 128
    const float* pr = g_chart_p + (((size_t)b * LL + 0) * LL + (LL - 1)) * SS;
    __shared__ float red[128];
    red[t] = pr[t] * starts[t];
    __syncthreads();
    for (int off = 64; off > 0; off >>= 1) {
        if (t < off) red[t] += red[t + off];
        __syncthreads();
    }
    float score = red[0];
    const float* fr = g_chart_f + (((size_t)b * LL + 0) * LL + (LL - 1)) * SDD;
    for (int h = t; h < SDD; h += 128) out[b * SDD + h] = fr[h] * score;
}

// ---------------- launcher ----------------
extern "C" void kernel_launch(void* const* d_in, const int* in_sizes, int n_in,
                              void* d_out, int out_size) {
    const int*   word    = (const int*)d_in[0];
    const float* emb     = (const float*)d_in[1];
    const float* preterm = (const float*)d_in[2];
    const float* G       = (const float*)d_in[3];
    const float* starts  = (const float*)d_in[4];
    const float* Wp      = (const float*)d_in[5];
    const float* bp      = (const float*)d_in[6];
    const float* Wm      = (const float*)d_in[7];
    const float* bm      = (const float*)d_in[8];
    float* out = (float*)d_out;

    cudaFuncSetAttribute(k_scores, cudaFuncAttributeMaxDynamicSharedMemorySize, 65536);

    k_transG<<<4096, 256>>>(G);
    k_diag<<<BB * LL, 64>>>(word, preterm);
    k_feat0<<<dim3(32, 8), 256>>>(word, emb, Wp, bp);

    for (int ln = 2; ln <= LL; ln++) {
        int n = LL - ln + 1;
        int R = (ln - 1) * BB * n;
        k_scores<<<(R + 31) / 32, 128, 65536>>>(ln, n, R);
        k_combine<<<BB * n, 64>>>(ln, n);
        k_feat<<<dim3((R + 63) / 64, 8), 256>>>(ln, n, R, Wm, bm);
        k_reduce_f<<<(BB * n * SDD + 255) / 256, 256>>>(ln, n);
    }

    k_root<<<BB, 128>>>(starts, out);
}

// round 3
// speedup vs baseline: 1.0823x; 1.0823x over previous
#include <cuda_runtime.h>

#define BB 64
#define LL 32
#define NTS 64
#define SS 128
#define SDD 512
#define EMBD 512
#define VV 50000
#define EPSF 1e-9f

// ---------------- scratch (device globals, no allocation) ----------------
__device__ float g_chart_p[(size_t)BB * LL * LL * SS];   // [b][i][len][s]
__device__ float g_chart_f[(size_t)BB * LL * LL * SDD];  // [b][i][len][h]
__device__ float g_Gt[SS * SS * NTS];                    // [s][t][a]
__device__ float g_sbuf[(size_t)16384 * NTS];            // per-stage partial scores [split][r][a]
__device__ float g_w[16384];                             // per-stage weights
__device__ float g_tmpf[(size_t)16384 * SDD];            // per-stage feats

// ---------------- K_t: transpose G[a][s][t] -> Gt[s][t][a] ----------------
__global__ void k_transG(const float* __restrict__ G) {
    int idx = blockIdx.x * 256 + threadIdx.x;
    if (idx >= NTS * SS * SS) return;
    int a = idx / (SS * SS);
    int rem = idx % (SS * SS);
    int s = rem / SS;
    int t = rem % SS;
    g_Gt[(s * SS + t) * NTS + a] = G[idx];
}

// ---------------- K0: diagonal preterminal probabilities ----------------
__global__ void k_diag(const int* __restrict__ word, const float* __restrict__ preterm) {
    int cell = blockIdx.x;          // b*LL + i
    int t = threadIdx.x;            // 0..63
    int w = word[cell];
    float v = preterm[(size_t)t * VV + w];
    __shared__ float red[64];
    red[t] = v;
    __syncthreads();
    for (int off = 32; off > 0; off >>= 1) {
        if (t < off) red[t] += red[t + off];
        __syncthreads();
    }
    float inv = 1.0f / (red[0] + EPSF);
    float* dst = g_chart_p + ((size_t)cell * LL + 0) * SS;
    dst[NTS + t] = v * inv;
    dst[t] = 0.0f;
}

// ---------------- K1: feat0 = relu(emb[word] @ Wp + bp) ----------------
__global__ void k_feat0(const int* __restrict__ word, const float* __restrict__ emb,
                        const float* __restrict__ Wp, const float* __restrict__ bp) {
    __shared__ float As[16][64];
    __shared__ float Bs[16][64];
    int tid = threadIdx.x;
    int m0 = blockIdx.x * 64, n0 = blockIdx.y * 64;
    int lm = tid >> 2, lk = (tid & 3) * 4;
    int kb = tid >> 4, nb = (tid & 15) * 4;
    int tx = tid & 15, ty = tid >> 4;

    const float* arow = emb + (size_t)word[m0 + lm] * EMBD;
    float acc[4][4] = {};

    for (int k0 = 0; k0 < EMBD; k0 += 16) {
        float4 a4 = *(const float4*)(arow + k0 + lk);
        As[lk + 0][lm] = a4.x; As[lk + 1][lm] = a4.y;
        As[lk + 2][lm] = a4.z; As[lk + 3][lm] = a4.w;
        float4 b4 = *(const float4*)(Wp + (size_t)(k0 + kb) * SDD + n0 + nb);
        *(float4*)&Bs[kb][nb] = b4;
        __syncthreads();
#pragma unroll
        for (int k = 0; k < 16; k++) {
            float4 av = *(float4*)&As[k][ty * 4];
            float4 bv = *(float4*)&Bs[k][tx * 4];
            acc[0][0] += av.x * bv.x; acc[0][1] += av.x * bv.y; acc[0][2] += av.x * bv.z; acc[0][3] += av.x * bv.w;
            acc[1][0] += av.y * bv.x; acc[1][1] += av.y * bv.y; acc[1][2] += av.y * bv.z; acc[1][3] += av.y * bv.w;
            acc[2][0] += av.z * bv.x; acc[2][1] += av.z * bv.y; acc[2][2] += av.z * bv.z; acc[2][3] += av.z * bv.w;
            acc[3][0] += av.w * bv.x; acc[3][1] += av.w * bv.y; acc[3][2] += av.w * bv.z; acc[3][3] += av.w * bv.w;
        }
        __syncthreads();
    }
#pragma unroll
    for (int i = 0; i < 4; i++) {
        int r = m0 + ty * 4 + i;
        float* dst = g_chart_f + ((size_t)r * LL + 0) * SDD;
#pragma unroll
        for (int j = 0; j < 4; j++) {
            int c = n0 + tx * 4 + j;
            float v = acc[i][j] + bp[c];
            dst[c] = v > 0.0f ? v : 0.0f;
        }
    }
}

// ---------------- K2: score GEMM  S[r][a] = sum_{s,t} lp[s] rp[t] Gt[s][t][a] ----------------
// 256 threads: two 128-thread groups split the t-range; blockIdx.y splits the s-range.
// BM=32 rows, BN=64 (all a), TM=2, TN=8 per thread. 64 KB dynamic smem.
__global__ void k_scores(int ln, int n, int R, int ks) {
    extern __shared__ float smem[];
    float* lpT = smem;           // [128 s][32 c]
    float* rpT = smem + 4096;    // [128 t][32 c]
    float* gs  = smem + 8192;    // [128 t][64 a]

    int tid = threadIdx.x;       // 0..255
    int r0 = blockIdx.x * 32;
    int split = blockIdx.y;
    int sc = SS / ks;
    int s0 = split * sc;

    // stage lp/rp rows, transposed into smem (each thread: 1 row, 16-float chunk)
    {
        int c = tid >> 3, q = tid & 7;
        int r = r0 + c;
        bool valid = r < R;
        const float* lp = g_chart_p;
        const float* rp = g_chart_p;
        if (valid) {
            int d1 = r / (BB * n);
            int rem = r % (BB * n);
            int b = rem / n, j = rem % n;
            lp = g_chart_p + (((size_t)b * LL + j) * LL + d1) * SS;
            rp = g_chart_p + (((size_t)b * LL + (j + d1 + 1)) * LL + (ln - d1 - 2)) * SS;
        }
        float4 z4 = make_float4(0, 0, 0, 0);
#pragma unroll
        for (int i = 0; i < 16; i += 4) {
            int t = q * 16 + i;
            float4 l4 = valid ? *(const float4*)(lp + t) : z4;
            float4 r4 = valid ? *(const float4*)(rp + t) : z4;
            lpT[(t + 0) * 32 + c] = l4.x; lpT[(t + 1) * 32 + c] = l4.y;
            lpT[(t + 2) * 32 + c] = l4.z; lpT[(t + 3) * 32 + c] = l4.w;
            rpT[(t + 0) * 32 + c] = r4.x; rpT[(t + 1) * 32 + c] = r4.y;
            rpT[(t + 2) * 32 + c] = r4.z; rpT[(t + 3) * 32 + c] = r4.w;
        }
    }
    __syncthreads();

    int grp = tid >> 7;          // 0/1 -> t-halves
    int lt  = tid & 127;
    int ty = lt >> 3;            // 0..15 -> c0 = ty*2
    int tx = lt & 7;             // 0..7  -> a0 = tx*8
    int tbase = grp * 64;

    float acc0[8] = {};
    float acc1[8] = {};

    for (int si = 0; si < sc; si++) {
        int s = s0 + si;
        const float* gsl = g_Gt + (size_t)s * (SS * NTS);
#pragma unroll
        for (int i = 0; i < 8; i++) {
            int idx = (i * 256 + tid) * 4;
            *(float4*)&gs[idx] = *(const float4*)(gsl + idx);
        }
        __syncthreads();
        float2 lv = *(float2*)&lpT[s * 32 + ty * 2];
#pragma unroll 8
        for (int t = tbase; t < tbase + 64; t++) {
            float2 rv = *(float2*)&rpT[t * 32 + ty * 2];
            float p0 = lv.x * rv.x;
            float p1 = lv.y * rv.y;
            float4 g0 = *(float4*)&gs[t * 64 + tx * 8];
            float4 g1 = *(float4*)&gs[t * 64 + tx * 8 + 4];
            acc0[0] += p0 * g0.x; acc0[1] += p0 * g0.y; acc0[2] += p0 * g0.z; acc0[3] += p0 * g0.w;
            acc0[4] += p0 * g1.x; acc0[5] += p0 * g1.y; acc0[6] += p0 * g1.z; acc0[7] += p0 * g1.w;
            acc1[0] += p1 * g0.x; acc1[1] += p1 * g0.y; acc1[2] += p1 * g0.z; acc1[3] += p1 * g0.w;
            acc1[4] += p1 * g1.x; acc1[5] += p1 * g1.y; acc1[6] += p1 * g1.z; acc1[7] += p1 * g1.w;
        }
        __syncthreads();
    }

    // cross-group reduction: group 1 dumps accs to smem, group 0 adds + stores
    if (grp == 1) {
        float* red = gs + lt * 16;
#pragma unroll
        for (int i = 0; i < 8; i++) { red[i] = acc0[i]; red[8 + i] = acc1[i]; }
    }
    __syncthreads();
    if (grp == 0) {
        const float* red = gs + lt * 16;
#pragma unroll
        for (int i = 0; i < 8; i++) { acc0[i] += red[i]; acc1[i] += red[8 + i]; }

        int a0 = tx * 8;
        size_t base = (size_t)split * R;
        int r_a = r0 + ty * 2;
        if (r_a < R) {
            *(float4*)&g_sbuf[(base + r_a) * NTS + a0]     = make_float4(acc0[0], acc0[1], acc0[2], acc0[3]);
            *(float4*)&g_sbuf[(base + r_a) * NTS + a0 + 4] = make_float4(acc0[4], acc0[5], acc0[6], acc0[7]);
        }
        int r_b = r_a + 1;
        if (r_b < R) {
            *(float4*)&g_sbuf[(base + r_b) * NTS + a0]     = make_float4(acc1[0], acc1[1], acc1[2], acc1[3]);
            *(float4*)&g_sbuf[(base + r_b) * NTS + a0 + 4] = make_float4(acc1[4], acc1[5], acc1[6], acc1[7]);
        }
    }
}

// ---------------- K3: combine over d (and s-splits) -> p (chart_p) and weights w ----------------
__global__ void k_combine(int ln, int n, int R, int ks) {
    int cell = blockIdx.x;          // b*n + j
    int b = cell / n, j = cell % n;
    int t = threadIdx.x;            // 64 threads
    int nd = ln - 1;
    __shared__ float sm_mass[32];
    __shared__ float sm_M;

    if (t < nd) {
        int r = (t * BB + b) * n + j;
        float m = 0.0f;
        for (int sp = 0; sp < ks; sp++) {
            const float* p = g_sbuf + ((size_t)sp * R + r) * NTS;
            for (int a = 0; a < NTS; a++) m += p[a];
        }
        sm_mass[t] = m;
    }
    __syncthreads();
    if (t == 0) {
        float M = 0.0f;
        for (int d = 0; d < nd; d++) M += sm_mass[d];
        sm_M = M;
    }
    __syncthreads();
    float Minv = 1.0f / (sm_M + EPSF);
    if (t < nd) {
        int r = (t * BB + b) * n + j;
        g_w[r] = sm_mass[t] * Minv;
    }
    float sc = 0.0f;
    for (int d = 0; d < nd; d++) {
        int r = (d * BB + b) * n + j;
        for (int sp = 0; sp < ks; sp++)
            sc += g_sbuf[((size_t)sp * R + r) * NTS + t];
    }
    float* dst = g_chart_p + (((size_t)b * LL + j) * LL + (ln - 1)) * SS;
    dst[t] = sc * Minv;
    dst[NTS + t] = 0.0f;
}

// ---------------- K4: feature GEMM  tmpf[r] = w[r]*relu([lf|rf]@Wm + bm) ----------------
__global__ void k_feat(int ln, int n, int R,
                       const float* __restrict__ Wm, const float* __restrict__ bm) {
    __shared__ float As[16][64];
    __shared__ float Bs[16][64];
    int tid = threadIdx.x;
    int m0 = blockIdx.x * 64, n0 = blockIdx.y * 64;
    int lm = tid >> 2, lkq = (tid & 3) * 4;
    int kb = tid >> 4, nb = (tid & 15) * 4;
    int tx = tid & 15, ty = tid >> 4;

    int r = m0 + lm;
    bool valid = r < R;
    const float* lf = g_chart_f;
    const float* rf = g_chart_f;
    if (valid) {
        int d1 = r / (BB * n);
        int rem = r % (BB * n);
        int b = rem / n, j = rem % n;
        lf = g_chart_f + (((size_t)b * LL + j) * LL + d1) * SDD;
        rf = g_chart_f + (((size_t)b * LL + (j + d1 + 1)) * LL + (ln - d1 - 2)) * SDD;
    }
    float4 z4 = make_float4(0, 0, 0, 0);
    float acc[4][4] = {};

    for (int k0 = 0; k0 < 2 * SDD; k0 += 16) {
        const float* src = (k0 < SDD) ? lf : rf;
        int kk = k0 + lkq - (k0 < SDD ? 0 : SDD);
        float4 a4 = valid ? *(const float4*)(src + kk) : z4;
        As[lkq + 0][lm] = a4.x; As[lkq + 1][lm] = a4.y;
        As[lkq + 2][lm] = a4.z; As[lkq + 3][lm] = a4.w;
        float4 b4 = *(const float4*)(Wm + (size_t)(k0 + kb) * SDD + n0 + nb);
        *(float4*)&Bs[kb][nb] = b4;
        __syncthreads();
#pragma unroll
        for (int k = 0; k < 16; k++) {
            float4 av = *(float4*)&As[k][ty * 4];
            float4 bv = *(float4*)&Bs[k][tx * 4];
            acc[0][0] += av.x * bv.x; acc[0][1] += av.x * bv.y; acc[0][2] += av.x * bv.z; acc[0][3] += av.x * bv.w;
            acc[1][0] += av.y * bv.x; acc[1][1] += av.y * bv.y; acc[1][2] += av.y * bv.z; acc[1][3] += av.y * bv.w;
            acc[2][0] += av.z * bv.x; acc[2][1] += av.z * bv.y; acc[2][2] += av.z * bv.z; acc[2][3] += av.z * bv.w;
            acc[3][0] += av.w * bv.x; acc[3][1] += av.w * bv.y; acc[3][2] += av.w * bv.z; acc[3][3] += av.w * bv.w;
        }
        __syncthreads();
    }
#pragma unroll
    for (int i = 0; i < 4; i++) {
        int rr = m0 + ty * 4 + i;
        if (rr < R) {
            float wgt = g_w[rr];
#pragma unroll
            for (int j = 0; j < 4; j++) {
                int c = n0 + tx * 4 + j;
                float v = acc[i][j] + bm[c];
                v = v > 0.0f ? v : 0.0f;
                g_tmpf[(size_t)rr * SDD + c] = v * wgt;
            }
        }
    }
}

// ---------------- K5: reduce weighted feats over d -> chart_f ----------------
__global__ void k_reduce_f(int ln, int n) {
    int idx = blockIdx.x * 256 + threadIdx.x;
    int tot = BB * n * SDD;
    if (idx >= tot) return;
    int h = idx & (SDD - 1);
    int cell = idx >> 9;
    int b = cell / n, j = cell % n;
    float acc = 0.0f;
    for (int d1 = 0; d1 < ln - 1; d1++) {
        int r = (d1 * BB + b) * n + j;
        acc += g_tmpf[(size_t)r * SDD + h];
    }
    g_chart_f[(((size_t)b * LL + j) * LL + (ln - 1)) * SDD + h] = acc;
}

// ---------------- K6: root ----------------
__global__ void k_root(const float* __restrict__ starts, float* __restrict__ out) {
    int b = blockIdx.x;
    int t = threadIdx.x;   // 128
    const float* pr = g_chart_p + (((size_t)b * LL + 0) * LL + (LL - 1)) * SS;
    __shared__ float red[128];
    red[t] = pr[t] * starts[t];
    __syncthreads();
    for (int off = 64; off > 0; off >>= 1) {
        if (t < off) red[t] += red[t + off];
        __syncthreads();
    }
    float score = red[0];
    const float* fr = g_chart_f + (((size_t)b * LL + 0) * LL + (LL - 1)) * SDD;
    for (int h = t; h < SDD; h += 128) out[b * SDD + h] = fr[h] * score;
}

// ---------------- launcher ----------------
extern "C" void kernel_launch(void* const* d_in, const int* in_sizes, int n_in,
                              void* d_out, int out_size) {
    const int*   word    = (const int*)d_in[0];
    const float* emb     = (const float*)d_in[1];
    const float* preterm = (const float*)d_in[2];
    const float* G       = (const float*)d_in[3];
    const float* starts  = (const float*)d_in[4];
    const float* Wp      = (const float*)d_in[5];
    const float* bp      = (const float*)d_in[6];
    const float* Wm      = (const float*)d_in[7];
    const float* bm      = (const float*)d_in[8];
    float* out = (float*)d_out;

    cudaFuncSetAttribute(k_scores, cudaFuncAttributeMaxDynamicSharedMemorySize, 65536);

    k_transG<<<4096, 256>>>(G);
    k_diag<<<BB * LL, 64>>>(word, preterm);
    k_feat0<<<dim3(32, 8), 256>>>(word, emb, Wp, bp);

    for (int ln = 2; ln <= LL; ln++) {
        int n = LL - ln + 1;
        int R = (ln - 1) * BB * n;
        int nb = (R + 31) / 32;
        int ks = 1;
        while (nb * ks < 256 && ks < 8) ks <<= 1;   // s-split to fill the chip
        k_scores<<<dim3(nb, ks), 256, 65536>>>(ln, n, R, ks);
        k_combine<<<BB * n, 64>>>(ln, n, R, ks);
        k_feat<<<dim3((R + 63) / 64, 8), 256>>>(ln, n, R, Wm, bm);
        k_reduce_f<<<(BB * n * SDD + 255) / 256, 256>>>(ln, n);
    }

    k_root<<<BB, 128>>>(starts, out);
}

// round 6
// speedup vs baseline: 3.5892x; 3.3163x over previous
#include <cuda_runtime.h>
#include <cuda_bf16.h>
#include <cstdint>

#define BB 64
#define LL 32
#define NTS 64
#define SS 128
#define SDD 512
#define EMBD 512
#define VV 50000
#define EPSF 1e-9f

// ---------------- scratch (device globals, no allocation) ----------------
__device__ float g_chart_p[(size_t)BB * LL * LL * SS];
__device__ float g_chart_f[(size_t)BB * LL * LL * SDD];
__device__ float g_sbuf[(size_t)65536 * NTS];            // partial scores [split][r][a]
__device__ float g_w[16384];
__device__ float g_tmpf[(size_t)16384 * SDD];
// G pre-split bf16 hi/lo: [chunk(=s*2+half)][a(64)][k(64)] as bf16x2 words
__device__ unsigned int g_Bhi[256 * 64 * 32];
__device__ unsigned int g_Blo[256 * 64 * 32];

// ---------------- helpers ----------------
__device__ __forceinline__ uint32_t smem_u32(const void* p) {
    uint32_t a;
    asm("{ .reg .u64 t; cvta.to.shared.u64 t, %1; cvt.u32.u64 %0, t; }" : "=r"(a) : "l"(p));
    return a;
}
__device__ __forceinline__ uint32_t packbf(float hi, float lo) {
    uint32_t d;
    asm("cvt.rn.bf16x2.f32 %0, %1, %2;" : "=r"(d) : "f"(hi), "f"(lo));
    return d;
}
__device__ __forceinline__ float bflow(uint32_t v)  { return __uint_as_float(v << 16); }
__device__ __forceinline__ float bfhigh(uint32_t v) { return __uint_as_float(v & 0xffff0000u); }

#define LDMX4(r0, r1, r2, r3, addr) \
    asm volatile("ldmatrix.sync.aligned.m8n8.x4.shared.b16 {%0,%1,%2,%3}, [%4];" \
                 : "=r"(r0), "=r"(r1), "=r"(r2), "=r"(r3) : "r"(addr))

#define MMA(c, a0, a1, a2, a3, b0, b1) \
    asm volatile("mma.sync.aligned.m16n8k16.row.col.f32.bf16.bf16.f32 " \
                 "{%0,%1,%2,%3}, {%4,%5,%6,%7}, {%8,%9}, {%0,%1,%2,%3};" \
                 : "+f"((c)[0]), "+f"((c)[1]), "+f"((c)[2]), "+f"((c)[3]) \
                 : "r"(a0), "r"(a1), "r"(a2), "r"(a3), "r"(b0), "r"(b1))

// ---------------- K_prepB: G[a][s][t] -> bf16 hi/lo chunk blocks [chunk][a][k] ----------------
__global__ void k_prepB(const float* __restrict__ G) {
    int idx = blockIdx.x * 256 + threadIdx.x;      // over 64*128*64 t-pairs
    if (idx >= NTS * SS * 64) return;
    int a = idx / (SS * 64);
    int rem = idx % (SS * 64);
    int s = rem / 64;
    int t = (rem % 64) * 2;
    float v0 = G[((size_t)a * SS + s) * SS + t];
    float v1 = G[((size_t)a * SS + s) * SS + t + 1];
    __nv_bfloat16 h0 = __float2bfloat16(v0);
    __nv_bfloat16 h1 = __float2bfloat16(v1);
    __nv_bfloat16 l0 = __float2bfloat16(v0 - __bfloat162float(h0));
    __nv_bfloat16 l1 = __float2bfloat16(v1 - __bfloat162float(h1));
    unsigned hi = (uint32_t)__bfloat16_as_ushort(h0) | ((uint32_t)__bfloat16_as_ushort(h1) << 16);
    unsigned lo = (uint32_t)__bfloat16_as_ushort(l0) | ((uint32_t)__bfloat16_as_ushort(l1) << 16);
    int chunk = s * 2 + (t >> 6);
    int kk = t & 63;
    int dst = (chunk * 64 + a) * 32 + (kk >> 1);
    g_Bhi[dst] = hi;
    g_Blo[dst] = lo;
}

// ---------------- K0: diagonal preterminal probabilities ----------------
__global__ void k_diag(const int* __restrict__ word, const float* __restrict__ preterm) {
    int cell = blockIdx.x;
    int t = threadIdx.x;
    int w = word[cell];
    float v = preterm[(size_t)t * VV + w];
    __shared__ float red[64];
    red[t] = v;
    __syncthreads();
    for (int off = 32; off > 0; off >>= 1) {
        if (t < off) red[t] += red[t + off];
        __syncthreads();
    }
    float inv = 1.0f / (red[0] + EPSF);
    float* dst = g_chart_p + ((size_t)cell * LL + 0) * SS;
    dst[NTS + t] = v * inv;
    dst[t] = 0.0f;
}

// ---------------- K1: feat0 = relu(emb[word] @ Wp + bp) ----------------
__global__ void k_feat0(const int* __restrict__ word, const float* __restrict__ emb,
                        const float* __restrict__ Wp, const float* __restrict__ bp) {
    __shared__ float As[16][64];
    __shared__ float Bs[16][64];
    int tid = threadIdx.x;
    int m0 = blockIdx.x * 64, n0 = blockIdx.y * 64;
    int lm = tid >> 2, lk = (tid & 3) * 4;
    int kb = tid >> 4, nb = (tid & 15) * 4;
    int tx = tid & 15, ty = tid >> 4;

    const float* arow = emb + (size_t)word[m0 + lm] * EMBD;
    float acc[4][4] = {};

    for (int k0 = 0; k0 < EMBD; k0 += 16) {
        float4 a4 = *(const float4*)(arow + k0 + lk);
        As[lk + 0][lm] = a4.x; As[lk + 1][lm] = a4.y;
        As[lk + 2][lm] = a4.z; As[lk + 3][lm] = a4.w;
        float4 b4 = *(const float4*)(Wp + (size_t)(k0 + kb) * SDD + n0 + nb);
        *(float4*)&Bs[kb][nb] = b4;
        __syncthreads();
#pragma unroll
        for (int k = 0; k < 16; k++) {
            float4 av = *(float4*)&As[k][ty * 4];
            float4 bv = *(float4*)&Bs[k][tx * 4];
            acc[0][0] += av.x * bv.x; acc[0][1] += av.x * bv.y; acc[0][2] += av.x * bv.z; acc[0][3] += av.x * bv.w;
            acc[1][0] += av.y * bv.x; acc[1][1] += av.y * bv.y; acc[1][2] += av.y * bv.z; acc[1][3] += av.y * bv.w;
            acc[2][0] += av.z * bv.x; acc[2][1] += av.z * bv.y; acc[2][2] += av.z * bv.z; acc[2][3] += av.z * bv.w;
            acc[3][0] += av.w * bv.x; acc[3][1] += av.w * bv.y; acc[3][2] += av.w * bv.z; acc[3][3] += av.w * bv.w;
        }
        __syncthreads();
    }
#pragma unroll
    for (int i = 0; i < 4; i++) {
        int r = m0 + ty * 4 + i;
        float* dst = g_chart_f + ((size_t)r * LL + 0) * SDD;
#pragma unroll
        for (int j = 0; j < 4; j++) {
            int c = n0 + tx * 4 + j;
            float v = acc[i][j] + bp[c];
            dst[c] = v > 0.0f ? v : 0.0f;
        }
    }
}

// ---------------- K2: score GEMM on mma.sync (bf16 hi/lo, fp32 accum) ----------------
// CTA: 128 rows x 64 a. 8 warps, each warp 16 rows x all 64 a.
// K processed in chunks of 64 (one s, one t-half). A generated in registers.
// smem: rps 128x136 f32 (69632 B) | GH 64x72 bf16 (9216 B) | GL (9216 B) = 88064 B
#define SM_RPS 0
#define SM_GH  69632
#define SM_GL  78848
#define SM_TOT 88064

__global__ __launch_bounds__(256) void k_scores_mma(int ln, int n, int R, int ks) {
    extern __shared__ __align__(16) char smem[];
    float* rps = (float*)(smem + SM_RPS);
    char* GH = smem + SM_GH;
    char* GL = smem + SM_GL;
    uint32_t ghb = smem_u32(GH), glb = smem_u32(GL);

    int tid = threadIdx.x;
    int w = tid >> 5, lane = tid & 31;
    int g = lane >> 2, q = lane & 3;
    int r0 = blockIdx.x * 128;
    int split = blockIdx.y;
    int C = 256 / ks, chunk0 = split * C;

    // stage rp rows (zero for invalid rows)
    {
        int m = tid >> 1, hh = tid & 1;
        int r = r0 + m;
        const float* rp = g_chart_p;
        bool valid = r < R;
        if (valid) {
            int d1 = r / (BB * n);
            int rem = r % (BB * n);
            int b = rem / n, j = rem % n;
            rp = g_chart_p + (((size_t)b * LL + (j + d1 + 1)) * LL + (ln - d1 - 2)) * SS;
        }
        float4 z = make_float4(0, 0, 0, 0);
        float4* dst = (float4*)(rps + m * 136 + hh * 64);
        const float4* src = (const float4*)(rp + hh * 64);
#pragma unroll
        for (int i = 0; i < 16; i++) dst[i] = valid ? src[i] : z;
    }

    // lane's two A rows + lp pointers
    int ra = w * 16 + g, rb = ra + 8;
    int rga = r0 + ra, rgb = r0 + rb;
    bool va = rga < R, vb = rgb < R;
    const float* lpa_p = g_chart_p;
    const float* lpb_p = g_chart_p;
    if (va) {
        int d1 = rga / (BB * n); int rem = rga % (BB * n); int b = rem / n, j = rem % n;
        lpa_p = g_chart_p + (((size_t)b * LL + j) * LL + d1) * SS;
    }
    if (vb) {
        int d1 = rgb / (BB * n); int rem = rgb % (BB * n); int b = rem / n, j = rem % n;
        lpb_p = g_chart_p + (((size_t)b * LL + j) * LL + d1) * SS;
    }

    float acc[8][4];
#pragma unroll
    for (int i = 0; i < 8; i++)
#pragma unroll
        for (int jx = 0; jx < 4; jx++) acc[i][jx] = 0.0f;

    // prefetch first chunk
    uint4 ph0, ph1, pl0, pl1;
    {
        const uint4* sh = (const uint4*)g_Bhi + (size_t)chunk0 * 512;
        const uint4* sl = (const uint4*)g_Blo + (size_t)chunk0 * 512;
        ph0 = sh[tid]; ph1 = sh[tid + 256];
        pl0 = sl[tid]; pl1 = sl[tid + 256];
    }
    __syncthreads();   // rps visible

    int i0a = (tid >> 3) * 144 + (tid & 7) * 16;
    int i1a = ((tid + 256) >> 3) * 144 + (tid & 7) * 16;

    for (int c = 0; c < C; c++) {
        // store staged G chunk
        *(uint4*)(GH + i0a) = ph0;
        *(uint4*)(GH + i1a) = ph1;
        *(uint4*)(GL + i0a) = pl0;
        *(uint4*)(GL + i1a) = pl1;

        int gchunk = chunk0 + c;
        int s = gchunk >> 1, th = gchunk & 1;
        float lpa = va ? __ldg(lpa_p + s) : 0.0f;
        float lpb = vb ? __ldg(lpb_p + s) : 0.0f;
        __syncthreads();   // G chunk visible

        if (c + 1 < C) {   // prefetch next (overlaps with compute)
            const uint4* sh = (const uint4*)g_Bhi + (size_t)(gchunk + 1) * 512;
            const uint4* sl = (const uint4*)g_Blo + (size_t)(gchunk + 1) * 512;
            ph0 = sh[tid]; ph1 = sh[tid + 256];
            pl0 = sl[tid]; pl1 = sl[tid + 256];
        }

        const float* rpa = rps + ra * 136 + th * 64;
        const float* rpb = rps + rb * 136 + th * 64;

#pragma unroll
        for (int ki = 0; ki < 4; ki++) {
            int kl = ki * 16;
            // ---- A generation (registers only) ----
            float2 A0 = *(const float2*)(rpa + kl + 2 * q);
            float2 A1 = *(const float2*)(rpa + kl + 2 * q + 8);
            float2 B0 = *(const float2*)(rpb + kl + 2 * q);
            float2 B1 = *(const float2*)(rpb + kl + 2 * q + 8);
            float p00 = lpa * A0.x, p01 = lpa * A0.y;   // row ra, k low pair
            float p10 = lpb * B0.x, p11 = lpb * B0.y;   // row rb, k low pair
            float p20 = lpa * A1.x, p21 = lpa * A1.y;   // row ra, k high pair
            float p30 = lpb * B1.x, p31 = lpb * B1.y;   // row rb, k high pair
            uint32_t ah0 = packbf(p01, p00);
            uint32_t ah1 = packbf(p11, p10);
            uint32_t ah2 = packbf(p21, p20);
            uint32_t ah3 = packbf(p31, p30);
            uint32_t al0 = packbf(p01 - bfhigh(ah0), p00 - bflow(ah0));
            uint32_t al1 = packbf(p11 - bfhigh(ah1), p10 - bflow(ah1));
            uint32_t al2 = packbf(p21 - bfhigh(ah2), p20 - bflow(ah2));
            uint32_t al3 = packbf(p31 - bfhigh(ah3), p30 - bflow(ah3));

            // ---- B ldmatrix + MMAs, 2 n-tiles per pair ----
            int sub = lane >> 3, ri = lane & 7;
            int koff2 = (kl + ((sub & 1) << 3)) * 2;
            int rowoff = (((sub >> 1) << 3) + ri) * 144 + koff2;
#pragma unroll
            for (int p = 0; p < 4; p++) {
                uint32_t addr_off = p * (16 * 144) + rowoff;
                uint32_t h0, h1, h2, h3, l0, l1, l2, l3;
                LDMX4(h0, h1, h2, h3, ghb + addr_off);
                LDMX4(l0, l1, l2, l3, glb + addr_off);
                MMA(acc[2 * p],     ah0, ah1, ah2, ah3, h0, h1);
                MMA(acc[2 * p],     ah0, ah1, ah2, ah3, l0, l1);
                MMA(acc[2 * p],     al0, al1, al2, al3, h0, h1);
                MMA(acc[2 * p + 1], ah0, ah1, ah2, ah3, h2, h3);
                MMA(acc[2 * p + 1], ah0, ah1, ah2, ah3, l2, l3);
                MMA(acc[2 * p + 1], al0, al1, al2, al3, h2, h3);
            }
        }
        __syncthreads();   // all reads done before next STS
    }

    // epilogue
    size_t base = (size_t)split * R;
#pragma unroll
    for (int nt = 0; nt < 8; nt++) {
        int aa = nt * 8 + 2 * q;
        if (va) *(float2*)(g_sbuf + (base + rga) * NTS + aa) = make_float2(acc[nt][0], acc[nt][1]);
        if (vb) *(float2*)(g_sbuf + (base + rgb) * NTS + aa) = make_float2(acc[nt][2], acc[nt][3]);
    }
}

// ---------------- K3: combine over d (and s-splits) ----------------
__global__ void k_combine(int ln, int n, int R, int ks) {
    int cell = blockIdx.x;
    int b = cell / n, j = cell % n;
    int t = threadIdx.x;            // 64
    int nd = ln - 1;
    __shared__ float sm_mass[32];
    __shared__ float sm_M;

    if (t < nd) {
        int r = (t * BB + b) * n + j;
        float m = 0.0f;
        for (int sp = 0; sp < ks; sp++) {
            const float* p = g_sbuf + ((size_t)sp * R + r) * NTS;
            for (int a = 0; a < NTS; a++) m += p[a];
        }
        sm_mass[t] = m;
    }
    __syncthreads();
    if (t == 0) {
        float M = 0.0f;
        for (int d = 0; d < nd; d++) M += sm_mass[d];
        sm_M = M;
    }
    __syncthreads();
    float Minv = 1.0f / (sm_M + EPSF);
    if (t < nd) {
        int r = (t * BB + b) * n + j;
        g_w[r] = sm_mass[t] * Minv;
    }
    float sc = 0.0f;
    for (int d = 0; d < nd; d++) {
        int r = (d * BB + b) * n + j;
        for (int sp = 0; sp < ks; sp++)
            sc += g_sbuf[((size_t)sp * R + r) * NTS + t];
    }
    float* dst = g_chart_p + (((size_t)b * LL + j) * LL + (ln - 1)) * SS;
    dst[t] = sc * Minv;
    dst[NTS + t] = 0.0f;
}

// ---------------- K4: feature GEMM 128x128 tile, TM=8 TN=8 ----------------
__global__ __launch_bounds__(256) void k_feat(int ln, int n, int R,
                                              const float* __restrict__ Wm,
                                              const float* __restrict__ bm) {
    __shared__ float As[8][132];
    __shared__ float Bs[8][132];
    int tid = threadIdx.x;
    int m0 = blockIdx.x * 128, n0 = blockIdx.y * 128;
    int row = tid >> 1, kh = tid & 1;
    int wk = tid >> 5, wn = (tid & 31) * 4;
    int tx = tid & 15, ty = tid >> 4;

    int r = m0 + row;
    bool valid = r < R;
    const float* lf = g_chart_f;
    const float* rf = g_chart_f;
    if (valid) {
        int d1 = r / (BB * n);
        int rem = r % (BB * n);
        int b = rem / n, j = rem % n;
        lf = g_chart_f + (((size_t)b * LL + j) * LL + d1) * SDD;
        rf = g_chart_f + (((size_t)b * LL + (j + d1 + 1)) * LL + (ln - d1 - 2)) * SDD;
    }
    float4 z4 = make_float4(0, 0, 0, 0);
    float acc[8][8] = {};

    for (int k0 = 0; k0 < 2 * SDD; k0 += 8) {
        const float* src = (k0 < SDD) ? lf : rf;
        int kk = k0 - (k0 < SDD ? 0 : SDD) + kh * 4;
        float4 a4 = valid ? *(const float4*)(src + kk) : z4;
        As[kh * 4 + 0][row] = a4.x; As[kh * 4 + 1][row] = a4.y;
        As[kh * 4 + 2][row] = a4.z; As[kh * 4 + 3][row] = a4.w;
        float4 b4 = *(const float4*)(Wm + (size_t)(k0 + wk) * SDD + n0 + wn);
        *(float4*)&Bs[wk][wn] = b4;
        __syncthreads();
#pragma unroll
        for (int k = 0; k < 8; k++) {
            float4 a0 = *(float4*)&As[k][ty * 8];
            float4 a1 = *(float4*)&As[k][ty * 8 + 4];
            float4 b0 = *(float4*)&Bs[k][tx * 8];
            float4 b1 = *(float4*)&Bs[k][tx * 8 + 4];
            float av[8] = {a0.x, a0.y, a0.z, a0.w, a1.x, a1.y, a1.z, a1.w};
            float bv[8] = {b0.x, b0.y, b0.z, b0.w, b1.x, b1.y, b1.z, b1.w};
#pragma unroll
            for (int i = 0; i < 8; i++)
#pragma unroll
                for (int jx = 0; jx < 8; jx++)
                    acc[i][jx] += av[i] * bv[jx];
        }
        __syncthreads();
    }
#pragma unroll
    for (int i = 0; i < 8; i++) {
        int rr = m0 + ty * 8 + i;
        if (rr < R) {
            float wgt = g_w[rr];
#pragma unroll
            for (int jx = 0; jx < 8; jx += 4) {
                int c = n0 + tx * 8 + jx;
                float v0 = acc[i][jx + 0] + bm[c + 0];
                float v1 = acc[i][jx + 1] + bm[c + 1];
                float v2 = acc[i][jx + 2] + bm[c + 2];
                float v3 = acc[i][jx + 3] + bm[c + 3];
                v0 = v0 > 0.f ? v0 : 0.f; v1 = v1 > 0.f ? v1 : 0.f;
                v2 = v2 > 0.f ? v2 : 0.f; v3 = v3 > 0.f ? v3 : 0.f;
                *(float4*)(g_tmpf + (size_t)rr * SDD + c) =
                    make_float4(v0 * wgt, v1 * wgt, v2 * wgt, v3 * wgt);
            }
        }
    }
}

// ---------------- K5: reduce weighted feats over d -> chart_f ----------------
__global__ void k_reduce_f(int ln, int n) {
    int idx = blockIdx.x * 256 + threadIdx.x;
    int tot = BB * n * SDD;
    if (idx >= tot) return;
    int h = idx & (SDD - 1);
    int cell = idx >> 9;
    int b = cell / n, j = cell % n;
    float acc = 0.0f;
    for (int d1 = 0; d1 < ln - 1; d1++) {
        int r = (d1 * BB + b) * n + j;
        acc += g_tmpf[(size_t)r * SDD + h];
    }
    g_chart_f[(((size_t)b * LL + j) * LL + (ln - 1)) * SDD + h] = acc;
}

// ---------------- K6: root ----------------
__global__ void k_root(const float* __restrict__ starts, float* __restrict__ out) {
    int b = blockIdx.x;
    int t = threadIdx.x;   // 128
    const float* pr = g_chart_p + (((size_t)b * LL + 0) * LL + (LL - 1)) * SS;
    __shared__ float red[128];
    red[t] = pr[t] * starts[t];
    __syncthreads();
    for (int off = 64; off > 0; off >>= 1) {
        if (t < off) red[t] += red[t + off];
        __syncthreads();
    }
    float score = red[0];
    const float* fr = g_chart_f + (((size_t)b * LL + 0) * LL + (LL - 1)) * SDD;
    for (int h = t; h < SDD; h += 128) out[b * SDD + h] = fr[h] * score;
}

// ---------------- launcher ----------------
extern "C" void kernel_launch(void* const* d_in, const int* in_sizes, int n_in,
                              void* d_out, int out_size) {
    const int*   word    = (const int*)d_in[0];
    const float* emb     = (const float*)d_in[1];
    const float* preterm = (const float*)d_in[2];
    const float* G       = (const float*)d_in[3];
    const float* starts  = (const float*)d_in[4];
    const float* Wp      = (const float*)d_in[5];
    const float* bp      = (const float*)d_in[6];
    const float* Wm      = (const float*)d_in[7];
    const float* bm      = (const float*)d_in[8];
    float* out = (float*)d_out;

    cudaFuncSetAttribute(k_scores_mma, cudaFuncAttributeMaxDynamicSharedMemorySize, SM_TOT);

    k_prepB<<<(NTS * SS * 64 + 255) / 256, 256>>>(G);
    k_diag<<<BB * LL, 64>>>(word, preterm);
    k_feat0<<<dim3(32, 8), 256>>>(word, emb, Wp, bp);

    for (int ln = 2; ln <= LL; ln++) {
        int n = LL - ln + 1;
        int R = (ln - 1) * BB * n;
        int tiles = (R + 127) / 128;
        int ks = 1;
        while (tiles * ks < 256 && ks < 16) ks <<= 1;
        k_scores_mma<<<dim3(tiles, ks), 256, SM_TOT>>>(ln, n, R, ks);
        k_combine<<<BB * n, 64>>>(ln, n, R, ks);
        k_feat<<<dim3(tiles, 4), 256>>>(ln, n, R, Wm, bm);
        k_reduce_f<<<(BB * n * SDD + 255) / 256, 256>>>(ln, n);
    }

    k_root<<<BB, 128>>>(starts, out);
}

// round 8
// speedup vs baseline: 7.8882x; 2.1977x over previous
#include <cuda_runtime.h>
#include <cuda_bf16.h>
#include <cstdint>

#define BB 64
#define LL 32
#define NTS 64
#define SS 128
#define SDD 512
#define EMBD 512
#define VV 50000
#define EPSF 1e-9f

// ---------------- scratch (device globals, no allocation) ----------------
__device__ __align__(16) float g_chart_p[(size_t)BB * LL * LL * SS];
__device__ __align__(16) float g_chart_f[(size_t)BB * LL * LL * SDD];
__device__ __align__(16) float g_sbuf[(size_t)65536 * NTS];      // partial scores [split][r][a]
__device__ __align__(16) float g_w[16384];
__device__ __align__(16) float g_uv[(size_t)BB * LL * LL * 1024]; // per-cell u(512)|v(512)
// G pre-split bf16 hi/lo: [chunk(=s*2+half)][a(64)][k(64)] as bf16x2 words
__device__ __align__(16) unsigned int g_Bhi[256 * 64 * 32];
__device__ __align__(16) unsigned int g_Blo[256 * 64 * 32];
// Wm transposed + split: [nn(1024)][k(512)] as bf16x2 words [1024][256]
__device__ __align__(16) unsigned int g_WmThi[1024 * 256];
__device__ __align__(16) unsigned int g_WmTlo[1024 * 256];

// ---------------- helpers ----------------
__device__ __forceinline__ uint32_t smem_u32(const void* p) {
    uint32_t a;
    asm("{ .reg .u64 t; cvta.to.shared.u64 t, %1; cvt.u32.u64 %0, t; }" : "=r"(a) : "l"(p));
    return a;
}
__device__ __forceinline__ uint32_t packbf(float hi, float lo) {
    uint32_t d;
    asm("cvt.rn.bf16x2.f32 %0, %1, %2;" : "=r"(d) : "f"(hi), "f"(lo));
    return d;
}
__device__ __forceinline__ float bflow(uint32_t v)  { return __uint_as_float(v << 16); }
__device__ __forceinline__ float bfhigh(uint32_t v) { return __uint_as_float(v & 0xffff0000u); }

#define LDMX4(r0, r1, r2, r3, addr) \
    asm volatile("ldmatrix.sync.aligned.m8n8.x4.shared.b16 {%0,%1,%2,%3}, [%4];" \
                 : "=r"(r0), "=r"(r1), "=r"(r2), "=r"(r3) : "r"(addr))

#define MMA(c, a0, a1, a2, a3, b0, b1) \
    asm volatile("mma.sync.aligned.m16n8k16.row.col.f32.bf16.bf16.f32 " \
                 "{%0,%1,%2,%3}, {%4,%5,%6,%7}, {%8,%9}, {%0,%1,%2,%3};" \
                 : "+f"((c)[0]), "+f"((c)[1]), "+f"((c)[2]), "+f"((c)[3]) \
                 : "r"(a0), "r"(a1), "r"(a2), "r"(a3), "r"(b0), "r"(b1))

// ---------------- K_prepB: G[a][s][t] -> bf16 hi/lo chunk blocks [chunk][a][k] ----------------
__global__ void k_prepB(const float* __restrict__ G) {
    int idx = blockIdx.x * 256 + threadIdx.x;      // over 64*128*64 t-pairs
    if (idx >= NTS * SS * 64) return;
    int a = idx / (SS * 64);
    int rem = idx % (SS * 64);
    int s = rem / 64;
    int t = (rem % 64) * 2;
    float v0 = G[((size_t)a * SS + s) * SS + t];
    float v1 = G[((size_t)a * SS + s) * SS + t + 1];
    __nv_bfloat16 h0 = __float2bfloat16(v0);
    __nv_bfloat16 h1 = __float2bfloat16(v1);
    __nv_bfloat16 l0 = __float2bfloat16(v0 - __bfloat162float(h0));
    __nv_bfloat16 l1 = __float2bfloat16(v1 - __bfloat162float(h1));
    unsigned hi = (uint32_t)__bfloat16_as_ushort(h0) | ((uint32_t)__bfloat16_as_ushort(h1) << 16);
    unsigned lo = (uint32_t)__bfloat16_as_ushort(l0) | ((uint32_t)__bfloat16_as_ushort(l1) << 16);
    int chunk = s * 2 + (t >> 6);
    int kk = t & 63;
    int dst = (chunk * 64 + a) * 32 + (kk >> 1);
    g_Bhi[dst] = hi;
    g_Blo[dst] = lo;
}

// ---------------- K_prepWm: Wm[1024][512] -> WmT[nn][k] bf16 hi/lo ----------------
// nn<512: WmT[nn][k] = Wm[k][nn] ; nn>=512: WmT[nn][k] = Wm[512+k][nn-512]
__global__ void k_prepWm(const float* __restrict__ Wm) {
    int idx = blockIdx.x * 256 + threadIdx.x;      // over 1024*256 words
    if (idx >= 1024 * 256) return;
    int nn = idx >> 8;
    int kw = idx & 255;
    int k0 = kw * 2;
    int roff = (nn < 512) ? 0 : 512;
    int col = nn - roff;
    float v0 = Wm[(size_t)(roff + k0) * SDD + col];
    float v1 = Wm[(size_t)(roff + k0 + 1) * SDD + col];
    __nv_bfloat16 h0 = __float2bfloat16(v0);
    __nv_bfloat16 h1 = __float2bfloat16(v1);
    __nv_bfloat16 l0 = __float2bfloat16(v0 - __bfloat162float(h0));
    __nv_bfloat16 l1 = __float2bfloat16(v1 - __bfloat162float(h1));
    g_WmThi[idx] = (uint32_t)__bfloat16_as_ushort(h0) | ((uint32_t)__bfloat16_as_ushort(h1) << 16);
    g_WmTlo[idx] = (uint32_t)__bfloat16_as_ushort(l0) | ((uint32_t)__bfloat16_as_ushort(l1) << 16);
}

// ---------------- K0: diagonal preterminal probabilities ----------------
__global__ void k_diag(const int* __restrict__ word, const float* __restrict__ preterm) {
    int cell = blockIdx.x;
    int t = threadIdx.x;
    int w = word[cell];
    float v = preterm[(size_t)t * VV + w];
    __shared__ float red[64];
    red[t] = v;
    __syncthreads();
    for (int off = 32; off > 0; off >>= 1) {
        if (t < off) red[t] += red[t + off];
        __syncthreads();
    }
    float inv = 1.0f / (red[0] + EPSF);
    float* dst = g_chart_p + ((size_t)cell * LL + 0) * SS;
    dst[NTS + t] = v * inv;
    dst[t] = 0.0f;
}

// ---------------- K1: feat0 = relu(emb[word] @ Wp + bp) ----------------
__global__ void k_feat0(const int* __restrict__ word, const float* __restrict__ emb,
                        const float* __restrict__ Wp, const float* __restrict__ bp) {
    __shared__ float As[16][64];
    __shared__ float Bs[16][64];
    int tid = threadIdx.x;
    int m0 = blockIdx.x * 64, n0 = blockIdx.y * 64;
    int lm = tid >> 2, lk = (tid & 3) * 4;
    int kb = tid >> 4, nb = (tid & 15) * 4;
    int tx = tid & 15, ty = tid >> 4;

    const float* arow = emb + (size_t)word[m0 + lm] * EMBD;
    float acc[4][4] = {};

    for (int k0 = 0; k0 < EMBD; k0 += 16) {
        float4 a4 = *(const float4*)(arow + k0 + lk);
        As[lk + 0][lm] = a4.x; As[lk + 1][lm] = a4.y;
        As[lk + 2][lm] = a4.z; As[lk + 3][lm] = a4.w;
        float4 b4 = *(const float4*)(Wp + (size_t)(k0 + kb) * SDD + n0 + nb);
        *(float4*)&Bs[kb][nb] = b4;
        __syncthreads();
#pragma unroll
        for (int k = 0; k < 16; k++) {
            float4 av = *(float4*)&As[k][ty * 4];
            float4 bv = *(float4*)&Bs[k][tx * 4];
            acc[0][0] += av.x * bv.x; acc[0][1] += av.x * bv.y; acc[0][2] += av.x * bv.z; acc[0][3] += av.x * bv.w;
            acc[1][0] += av.y * bv.x; acc[1][1] += av.y * bv.y; acc[1][2] += av.y * bv.z; acc[1][3] += av.y * bv.w;
            acc[2][0] += av.z * bv.x; acc[2][1] += av.z * bv.y; acc[2][2] += av.z * bv.z; acc[2][3] += av.z * bv.w;
            acc[3][0] += av.w * bv.x; acc[3][1] += av.w * bv.y; acc[3][2] += av.w * bv.z; acc[3][3] += av.w * bv.w;
        }
        __syncthreads();
    }
#pragma unroll
    for (int i = 0; i < 4; i++) {
        int r = m0 + ty * 4 + i;
        float* dst = g_chart_f + ((size_t)r * LL + 0) * SDD;
#pragma unroll
        for (int j = 0; j < 4; j++) {
            int c = n0 + tx * 4 + j;
            float v = acc[i][j] + bp[c];
            dst[c] = v > 0.0f ? v : 0.0f;
        }
    }
}

// ---------------- K2: score GEMM on mma.sync (bf16 hi/lo, fp32 accum) ----------------
#define SM_RPS 0
#define SM_GH  69632
#define SM_GL  78848
#define SM_TOT 88064

__global__ __launch_bounds__(256) void k_scores_mma(int ln, int n, int R, int ks) {
    extern __shared__ __align__(16) char smem[];
    float* rps = (float*)(smem + SM_RPS);
    char* GH = smem + SM_GH;
    char* GL = smem + SM_GL;
    uint32_t ghb = smem_u32(GH), glb = smem_u32(GL);

    int tid = threadIdx.x;
    int w = tid >> 5, lane = tid & 31;
    int g = lane >> 2, q = lane & 3;
    int r0 = blockIdx.x * 128;
    int split = blockIdx.y;
    int C = 256 / ks, chunk0 = split * C;

    // stage rp rows (zero for invalid rows)
    {
        int m = tid >> 1, hh = tid & 1;
        int r = r0 + m;
        const float* rp = g_chart_p;
        bool valid = r < R;
        if (valid) {
            int d1 = r / (BB * n);
            int rem = r % (BB * n);
            int b = rem / n, j = rem % n;
            rp = g_chart_p + (((size_t)b * LL + (j + d1 + 1)) * LL + (ln - d1 - 2)) * SS;
        }
        float4 z = make_float4(0, 0, 0, 0);
        float4* dst = (float4*)(rps + m * 136 + hh * 64);
        const float4* src = (const float4*)(rp + hh * 64);
#pragma unroll
        for (int i = 0; i < 16; i++) dst[i] = valid ? src[i] : z;
    }

    int ra = w * 16 + g, rb = ra + 8;
    int rga = r0 + ra, rgb = r0 + rb;
    bool va = rga < R, vb = rgb < R;
    const float* lpa_p = g_chart_p;
    const float* lpb_p = g_chart_p;
    if (va) {
        int d1 = rga / (BB * n); int rem = rga % (BB * n); int b = rem / n, j = rem % n;
        lpa_p = g_chart_p + (((size_t)b * LL + j) * LL + d1) * SS;
    }
    if (vb) {
        int d1 = rgb / (BB * n); int rem = rgb % (BB * n); int b = rem / n, j = rem % n;
        lpb_p = g_chart_p + (((size_t)b * LL + j) * LL + d1) * SS;
    }

    float acc[8][4];
#pragma unroll
    for (int i = 0; i < 8; i++)
#pragma unroll
        for (int jx = 0; jx < 4; jx++) acc[i][jx] = 0.0f;

    uint4 ph0, ph1, pl0, pl1;
    {
        const uint4* sh = (const uint4*)g_Bhi + (size_t)chunk0 * 512;
        const uint4* sl = (const uint4*)g_Blo + (size_t)chunk0 * 512;
        ph0 = sh[tid]; ph1 = sh[tid + 256];
        pl0 = sl[tid]; pl1 = sl[tid + 256];
    }
    __syncthreads();

    int i0a = (tid >> 3) * 144 + (tid & 7) * 16;
    int i1a = ((tid + 256) >> 3) * 144 + (tid & 7) * 16;

    for (int c = 0; c < C; c++) {
        *(uint4*)(GH + i0a) = ph0;
        *(uint4*)(GH + i1a) = ph1;
        *(uint4*)(GL + i0a) = pl0;
        *(uint4*)(GL + i1a) = pl1;

        int gchunk = chunk0 + c;
        int s = gchunk >> 1, th = gchunk & 1;
        float lpa = va ? __ldg(lpa_p + s) : 0.0f;
        float lpb = vb ? __ldg(lpb_p + s) : 0.0f;
        __syncthreads();

        if (c + 1 < C) {
            const uint4* sh = (const uint4*)g_Bhi + (size_t)(gchunk + 1) * 512;
            const uint4* sl = (const uint4*)g_Blo + (size_t)(gchunk + 1) * 512;
            ph0 = sh[tid]; ph1 = sh[tid + 256];
            pl0 = sl[tid]; pl1 = sl[tid + 256];
        }

        const float* rpa = rps + ra * 136 + th * 64;
        const float* rpb = rps + rb * 136 + th * 64;

#pragma unroll
        for (int ki = 0; ki < 4; ki++) {
            int kl = ki * 16;
            float2 A0 = *(const float2*)(rpa + kl + 2 * q);
            float2 A1 = *(const float2*)(rpa + kl + 2 * q + 8);
            float2 B0 = *(const float2*)(rpb + kl + 2 * q);
            float2 B1 = *(const float2*)(rpb + kl + 2 * q + 8);
            float p00 = lpa * A0.x, p01 = lpa * A0.y;
            float p10 = lpb * B0.x, p11 = lpb * B0.y;
            float p20 = lpa * A1.x, p21 = lpa * A1.y;
            float p30 = lpb * B1.x, p31 = lpb * B1.y;
            uint32_t ah0 = packbf(p01, p00);
            uint32_t ah1 = packbf(p11, p10);
            uint32_t ah2 = packbf(p21, p20);
            uint32_t ah3 = packbf(p31, p30);
            uint32_t al0 = packbf(p01 - bfhigh(ah0), p00 - bflow(ah0));
            uint32_t al1 = packbf(p11 - bfhigh(ah1), p10 - bflow(ah1));
            uint32_t al2 = packbf(p21 - bfhigh(ah2), p20 - bflow(ah2));
            uint32_t al3 = packbf(p31 - bfhigh(ah3), p30 - bflow(ah3));

            int sub = lane >> 3, ri = lane & 7;
            int koff2 = (kl + ((sub & 1) << 3)) * 2;
            int rowoff = (((sub >> 1) << 3) + ri) * 144 + koff2;
#pragma unroll
            for (int p = 0; p < 4; p++) {
                uint32_t addr_off = p * (16 * 144) + rowoff;
                uint32_t h0, h1, h2, h3, l0, l1, l2, l3;
                LDMX4(h0, h1, h2, h3, ghb + addr_off);
                LDMX4(l0, l1, l2, l3, glb + addr_off);
                MMA(acc[2 * p],     ah0, ah1, ah2, ah3, h0, h1);
                MMA(acc[2 * p],     ah0, ah1, ah2, ah3, l0, l1);
                MMA(acc[2 * p],     al0, al1, al2, al3, h0, h1);
                MMA(acc[2 * p + 1], ah0, ah1, ah2, ah3, h2, h3);
                MMA(acc[2 * p + 1], ah0, ah1, ah2, ah3, l2, l3);
                MMA(acc[2 * p + 1], al0, al1, al2, al3, h2, h3);
            }
        }
        __syncthreads();
    }

    size_t base = (size_t)split * R;
#pragma unroll
    for (int nt = 0; nt < 8; nt++) {
        int aa = nt * 8 + 2 * q;
        if (va) *(float2*)(g_sbuf + (base + rga) * NTS + aa) = make_float2(acc[nt][0], acc[nt][1]);
        if (vb) *(float2*)(g_sbuf + (base + rgb) * NTS + aa) = make_float2(acc[nt][2], acc[nt][3]);
    }
}

// ---------------- K3: combine over d (and s-splits) ----------------
__global__ void k_combine(int ln, int n, int R, int ks) {
    int cell = blockIdx.x;
    int b = cell / n, j = cell % n;
    int t = threadIdx.x;            // 64
    int nd = ln - 1;
    __shared__ float sm_mass[32];
    __shared__ float sm_M;

    if (t < nd) {
        int r = (t * BB + b) * n + j;
        float m = 0.0f;
        for (int sp = 0; sp < ks; sp++) {
            const float* p = g_sbuf + ((size_t)sp * R + r) * NTS;
            for (int a = 0; a < NTS; a++) m += p[a];
        }
        sm_mass[t] = m;
    }
    __syncthreads();
    if (t == 0) {
        float M = 0.0f;
        for (int d = 0; d < nd; d++) M += sm_mass[d];
        sm_M = M;
    }
    __syncthreads();
    float Minv = 1.0f / (sm_M + EPSF);
    if (t < nd) {
        int r = (t * BB + b) * n + j;
        g_w[r] = sm_mass[t] * Minv;
    }
    float sc = 0.0f;
    for (int d = 0; d < nd; d++) {
        int r = (d * BB + b) * n + j;
        for (int sp = 0; sp < ks; sp++)
            sc += g_sbuf[((size_t)sp * R + r) * NTS + t];
    }
    float* dst = g_chart_p + (((size_t)b * LL + j) * LL + (ln - 1)) * SS;
    dst[t] = sc * Minv;
    dst[NTS + t] = 0.0f;
}

// ---------------- K_uv: per-cell u|v = cell @ [Wm_top | Wm_bot]  (mma bf16 hi/lo) ----------------
// CTA: 128 rows x 128 cols. K=512 in chunks of 32. 8 warps, each 16 rows x 128 cols.
// UVP = 80 bytes pitch: multiple of 16 (alignment) and stride-20-words -> conflict-free ldmatrix.
#define UVP 80
__global__ __launch_bounds__(256) void k_uv(int ln, int n, int M) {
    __shared__ __align__(16) char sm[4 * 128 * UVP];  // Ahi | Alo | Bhi | Blo
    char* AH = sm;
    char* AL = sm + 128 * UVP;
    char* BH = sm + 2 * 128 * UVP;
    char* BL = sm + 3 * 128 * UVP;
    uint32_t ahb = smem_u32(AH), alb = smem_u32(AL);
    uint32_t bhb = smem_u32(BH), blb = smem_u32(BL);

    int tid = threadIdx.x;
    int w = tid >> 5, lane = tid & 31;
    int g = lane >> 2, q = lane & 3;
    int sub = lane >> 3, ri = lane & 7;
    int m0 = blockIdx.x * 128;
    int n0 = blockIdx.y * 128;

    // A staging ids: thread -> row am, k-half akh (16 k each)
    int am = tid >> 1, akh = tid & 1;
    int rs = m0 + am;
    bool vs = rs < M;
    const float* arow = g_chart_f;
    if (vs) {
        int b = rs / n, j = rs % n;
        arow = g_chart_f + (((size_t)b * LL + j) * LL + (ln - 1)) * SDD;
    }

    // epilogue row pointers
    int rga = m0 + w * 16 + g, rgb = rga + 8;
    bool va = rga < M, vb = rgb < M;
    float* dstA = g_uv;
    float* dstB = g_uv;
    if (va) { int b = rga / n, j = rga % n; dstA = g_uv + (((size_t)b * LL + j) * LL + (ln - 1)) * 1024; }
    if (vb) { int b = rgb / n, j = rgb % n; dstB = g_uv + (((size_t)b * LL + j) * LL + (ln - 1)) * 1024; }

    float acc[16][4];
#pragma unroll
    for (int i = 0; i < 16; i++)
#pragma unroll
        for (int jx = 0; jx < 4; jx++) acc[i][jx] = 0.0f;

    // B staging ids: 2 iterations, nn = it*64 + (tid>>2), e = tid&3
    int bnn = tid >> 2, be = tid & 3;

    // prefetch chunk 0
    float4 pa[4];
    uint4 pbh[2], pbl[2];
    {
        const float* asrc = arow + akh * 16;
        float4 z = make_float4(0, 0, 0, 0);
#pragma unroll
        for (int i = 0; i < 4; i++) pa[i] = vs ? *(const float4*)(asrc + 4 * i) : z;
        const uint4* wh = (const uint4*)g_WmThi;
        const uint4* wl = (const uint4*)g_WmTlo;
#pragma unroll
        for (int it = 0; it < 2; it++) {
            int nn = n0 + it * 64 + bnn;
            pbh[it] = wh[nn * 64 + be];
            pbl[it] = wl[nn * 64 + be];
        }
    }

    for (int kc = 0; kc < 16; kc++) {
        // store staged chunk
        {
            char* ah = AH + am * UVP + akh * 32;
            char* al = AL + am * UVP + akh * 32;
#pragma unroll
            for (int i = 0; i < 4; i++) {
                float4 av = pa[i];
                uint32_t h0 = packbf(av.y, av.x);
                uint32_t h1 = packbf(av.w, av.z);
                uint32_t l0 = packbf(av.y - bfhigh(h0), av.x - bflow(h0));
                uint32_t l1 = packbf(av.w - bfhigh(h1), av.z - bflow(h1));
                *(uint32_t*)(ah + 8 * i) = h0;
                *(uint32_t*)(ah + 8 * i + 4) = h1;
                *(uint32_t*)(al + 8 * i) = l0;
                *(uint32_t*)(al + 8 * i + 4) = l1;
            }
#pragma unroll
            for (int it = 0; it < 2; it++) {
                int nn = it * 64 + bnn;
                *(uint4*)(BH + nn * UVP + be * 16) = pbh[it];
                *(uint4*)(BL + nn * UVP + be * 16) = pbl[it];
            }
        }
        __syncthreads();

        if (kc + 1 < 16) {   // prefetch next chunk
            const float* asrc = arow + (kc + 1) * 32 + akh * 16;
            float4 z = make_float4(0, 0, 0, 0);
#pragma unroll
            for (int i = 0; i < 4; i++) pa[i] = vs ? *(const float4*)(asrc + 4 * i) : z;
            const uint4* wh = (const uint4*)g_WmThi;
            const uint4* wl = (const uint4*)g_WmTlo;
#pragma unroll
            for (int it = 0; it < 2; it++) {
                int nn = n0 + it * 64 + bnn;
                pbh[it] = wh[nn * 64 + (kc + 1) * 4 + be];
                pbl[it] = wl[nn * 64 + (kc + 1) * 4 + be];
            }
        }

#pragma unroll
        for (int kk = 0; kk < 32; kk += 16) {
            // A fragments
            uint32_t aoff = (w * 16 + (sub & 1) * 8 + ri) * UVP + (kk + (sub >> 1) * 8) * 2;
            uint32_t ah0, ah1, ah2, ah3, al0, al1, al2, al3;
            LDMX4(ah0, ah1, ah2, ah3, ahb + aoff);
            LDMX4(al0, al1, al2, al3, alb + aoff);

            uint32_t rowoff = ((sub >> 1) * 8 + ri) * UVP + (kk + (sub & 1) * 8) * 2;
#pragma unroll
            for (int p = 0; p < 8; p++) {
                uint32_t boff = p * (16 * UVP) + rowoff;
                uint32_t h0, h1, h2, h3, l0, l1, l2, l3;
                LDMX4(h0, h1, h2, h3, bhb + boff);
                LDMX4(l0, l1, l2, l3, blb + boff);
                MMA(acc[2 * p],     ah0, ah1, ah2, ah3, h0, h1);
                MMA(acc[2 * p],     ah0, ah1, ah2, ah3, l0, l1);
                MMA(acc[2 * p],     al0, al1, al2, al3, h0, h1);
                MMA(acc[2 * p + 1], ah0, ah1, ah2, ah3, h2, h3);
                MMA(acc[2 * p + 1], ah0, ah1, ah2, ah3, l2, l3);
                MMA(acc[2 * p + 1], al0, al1, al2, al3, h2, h3);
            }
        }
        __syncthreads();
    }

    // epilogue
#pragma unroll
    for (int nt = 0; nt < 16; nt++) {
        int cc = n0 + nt * 8 + 2 * q;
        if (va) *(float2*)(dstA + cc) = make_float2(acc[nt][0], acc[nt][1]);
        if (vb) *(float2*)(dstB + cc) = make_float2(acc[nt][2], acc[nt][3]);
    }
}

// ---------------- K_featcomb: chart_f[cell] = sum_d w * relu(u_l + v_r + bm) ----------------
__global__ void k_featcomb(int ln, int n, const float* __restrict__ bm) {
    int cell = blockIdx.x;
    int b = cell / n, j = cell % n;
    int t = threadIdx.x;           // 128
    int h = t * 4;
    float4 bmv = *(const float4*)(bm + h);
    float4 acc = make_float4(0, 0, 0, 0);
    int nd = ln - 1;
    for (int d1 = 0; d1 < nd; d1++) {
        int r = (d1 * BB + b) * n + j;
        float wgt = g_w[r];
        const float4 uu = *(const float4*)(g_uv + (((size_t)b * LL + j) * LL + d1) * 1024 + h);
        const float4 vv = *(const float4*)(g_uv + (((size_t)b * LL + (j + d1 + 1)) * LL + (ln - d1 - 2)) * 1024 + 512 + h);
        float x0 = uu.x + vv.x + bmv.x;
        float x1 = uu.y + vv.y + bmv.y;
        float x2 = uu.z + vv.z + bmv.z;
        float x3 = uu.w + vv.w + bmv.w;
        acc.x += wgt * (x0 > 0.f ? x0 : 0.f);
        acc.y += wgt * (x1 > 0.f ? x1 : 0.f);
        acc.z += wgt * (x2 > 0.f ? x2 : 0.f);
        acc.w += wgt * (x3 > 0.f ? x3 : 0.f);
    }
    *(float4*)(g_chart_f + (((size_t)b * LL + j) * LL + (ln - 1)) * SDD + h) = acc;
}

// ---------------- K6: root ----------------
__global__ void k_root(const float* __restrict__ starts, float* __restrict__ out) {
    int b = blockIdx.x;
    int t = threadIdx.x;   // 128
    const float* pr = g_chart_p + (((size_t)b * LL + 0) * LL + (LL - 1)) * SS;
    __shared__ float red[128];
    red[t] = pr[t] * starts[t];
    __syncthreads();
    for (int off = 64; off > 0; off >>= 1) {
        if (t < off) red[t] += red[t + off];
        __syncthreads();
    }
    float score = red[0];
    const float* fr = g_chart_f + (((size_t)b * LL + 0) * LL + (LL - 1)) * SDD;
    for (int h = t; h < SDD; h += 128) out[b * SDD + h] = fr[h] * score;
}

// ---------------- launcher ----------------
extern "C" void kernel_launch(void* const* d_in, const int* in_sizes, int n_in,
                              void* d_out, int out_size) {
    const int*   word    = (const int*)d_in[0];
    const float* emb     = (const float*)d_in[1];
    const float* preterm = (const float*)d_in[2];
    const float* G       = (const float*)d_in[3];
    const float* starts  = (const float*)d_in[4];
    const float* Wp      = (const float*)d_in[5];
    const float* bp      = (const float*)d_in[6];
    const float* Wm      = (const float*)d_in[7];
    const float* bm      = (const float*)d_in[8];
    float* out = (float*)d_out;

    cudaFuncSetAttribute(k_scores_mma, cudaFuncAttributeMaxDynamicSharedMemorySize, SM_TOT);

    k_prepB<<<(NTS * SS * 64 + 255) / 256, 256>>>(G);
    k_prepWm<<<(1024 * 256 + 255) / 256, 256>>>(Wm);
    k_diag<<<BB * LL, 64>>>(word, preterm);
    k_feat0<<<dim3(32, 8), 256>>>(word, emb, Wp, bp);
    // u,v for all len=1 cells (n=32 -> M=2048)
    k_uv<<<dim3(16, 8), 256>>>(1, 32, BB * 32);

    for (int ln = 2; ln <= LL; ln++) {
        int n = LL - ln + 1;
        int R = (ln - 1) * BB * n;
        int tiles = (R + 127) / 128;
        int ks = 1;
        while (tiles * ks < 256 && ks < 16) ks <<= 1;
        k_scores_mma<<<dim3(tiles, ks), 256, SM_TOT>>>(ln, n, R, ks);
        k_combine<<<BB * n, 64>>>(ln, n, R, ks);
        k_featcomb<<<BB * n, 128>>>(ln, n, bm);
        if (ln < LL) {
            int M = BB * n;
            k_uv<<<dim3((M + 127) / 128, 8), 256>>>(ln, n, M);
        }
    }

    k_root<<<BB, 128>>>(starts, out);
}